// round 14
// baseline (speedup 1.0000x reference)
#include <cuda_runtime.h>
#include <cuda_fp16.h>
#include <cstdint>

#define NB   16
#define NWAY 5
#define NQ   25
#define NSS  130
#define NQQ  75
#define CF   640
#define SRN  (NB*NWAY*NSS)   // 10400
#define TRN  (NB*NQQ*NQ)     // 30000
#define ROWB (CF*2)          // 1280 B per fp16 row
#define RS   144             // smem row stride (128B data + 16 pad)
#define NCH  10              // chunks of 64 fp16

__device__ __half g_S[SRN*CF];
__device__ __half g_T[TRN*CF];
__device__ float g_cS[SRN];          // exact inv-norm of fp16 row
__device__ float g_cT[TRN];
__device__ float g_ss_sum[NB*NWAY];
__device__ float g_mmd_q[NB*NQQ];
__device__ float g_qs_sum[NB*NQQ*NWAY];

// ---------------------------------------------------------------------------
__device__ __forceinline__ uint32_t smem_u32(const void* p) {
    uint32_t a;
    asm("{ .reg .u64 t; cvta.to.shared.u64 t, %1; cvt.u32.u64 %0, t; }"
        : "=r"(a) : "l"(p));
    return a;
}
__device__ __forceinline__ void ldsm_x4(uint32_t* r, uint32_t addr) {
    asm volatile("ldmatrix.sync.aligned.m8n8.x4.shared.b16 {%0,%1,%2,%3}, [%4];"
                 : "=r"(r[0]), "=r"(r[1]), "=r"(r[2]), "=r"(r[3]) : "r"(addr));
}
__device__ __forceinline__ void mma4(float* c, const uint32_t* a,
                                     uint32_t b0, uint32_t b1) {
    asm volatile(
        "mma.sync.aligned.m16n8k16.row.col.f32.f16.f16.f32 "
        "{%0,%1,%2,%3}, {%4,%5,%6,%7}, {%8,%9}, {%0,%1,%2,%3};"
        : "+f"(c[0]), "+f"(c[1]), "+f"(c[2]), "+f"(c[3])
        : "r"(a[0]), "r"(a[1]), "r"(a[2]), "r"(a[3]), "r"(b0), "r"(b1));
}
__device__ __forceinline__ void cp16(uint32_t dst, const void* src, int szp) {
    asm volatile("cp.async.cg.shared.global [%0], [%1], 16, %2;"
                 :: "r"(dst), "l"(src), "r"(szp));
}
#define CP_COMMIT() asm volatile("cp.async.commit_group;" ::: "memory")
#define CP_WAIT1()  asm volatile("cp.async.wait_group 1;" ::: "memory")
#define CP_WAIT0()  asm volatile("cp.async.wait_group 0;" ::: "memory")

__device__ __forceinline__ float multigauss_dot(float dot) {
    float d2 = fmaxf(2.0f - 2.0f * dot, 0.0f);
    float u  = __expf(-0.125f * d2);
    float u2 = u*u, u4 = u2*u2, u8 = u4*u4, u16 = u8*u8;
    return u + u2 + u4 + u8 + u16;
}

// ---------------------------------------------------------------------------
// normalize (+ zero accumulators): one warp per row -> fp16 row + exact c
__global__ __launch_bounds__(256) void norm_kernel(
    const float* __restrict__ sup, const float* __restrict__ qry) {
    int gt0 = blockIdx.x * 256 + threadIdx.x;
    if (gt0 < NB * NQQ * NWAY) g_qs_sum[gt0] = 0.f;
    if (gt0 < NB * NWAY) g_ss_sum[gt0] = 0.f;

    int row = blockIdx.x * 8 + (threadIdx.x >> 5);
    if (row >= SRN + TRN) return;
    int lane = threadIdx.x & 31;

    const float* src;
    __half* dst;
    float* cdst;
    if (row < SRN) {
        src = sup + (size_t)row * CF;
        dst = g_S + (size_t)row * CF;
        cdst = g_cS + row;
    } else {
        int r = row - SRN;
        src = qry + (size_t)r * CF;
        dst = g_T + (size_t)r * CF;
        cdst = g_cT + r;
    }

    float4 v[5];
    float s1 = 0.f, s2 = 0.f;
#pragma unroll
    for (int s = 0; s < 5; s++) {
        v[s] = ((const float4*)src)[s * 32 + lane];
        s1 += v[s].x + v[s].y + v[s].z + v[s].w;
        s2 += v[s].x*v[s].x + v[s].y*v[s].y + v[s].z*v[s].z + v[s].w*v[s].w;
    }
#pragma unroll
    for (int o = 16; o > 0; o >>= 1) {
        s1 += __shfl_xor_sync(0xffffffffu, s1, o);
        s2 += __shfl_xor_sync(0xffffffffu, s2, o);
    }
    float mean = s1 * (1.0f / CF);
    float inv = rsqrtf(s2 - s1 * mean + 1e-12f);

    float hh = 0.f;
    union { __half h[4]; uint2 u; } ph[5];
#pragma unroll
    for (int s = 0; s < 5; s++) {
        float x[4] = {(v[s].x - mean) * inv, (v[s].y - mean) * inv,
                      (v[s].z - mean) * inv, (v[s].w - mean) * inv};
#pragma unroll
        for (int k = 0; k < 4; k++) {
            __half hf = __float2half_rn(x[k]);
            ph[s].h[k] = hf;
            float hv = __half2float(hf);
            hh += hv * hv;
        }
    }
#pragma unroll
    for (int o = 16; o > 0; o >>= 1)
        hh += __shfl_xor_sync(0xffffffffu, hh, o);
    float rcorr = rsqrtf(hh + 1e-12f);

#pragma unroll
    for (int s = 0; s < 5; s++)
        ((uint2*)dst)[s * 32 + lane] = ph[s].u;
    if (lane == 0) *cdst = rcorr;
}

// ---------------------------------------------------------------------------
// mega kernel, 256 threads (128-reg cap at 2 CTA/SM):
//   [0,1200)    cross tiles 128x128 (S x T)
//   [1200,1280) kss diagonal tile 128x128 (S x S, offdiag sum)
//   [1280,1520) kqq (5 warps)
//   [1520,1760) rem (S rows 640-649 x T)
//   [1760,1840) kss boundary strips (scalar, 514 pairs each)
#define X_ARR   (128*RS)           // 18432
#define X_STAGE (2*X_ARR)          // 36864
#define X_SMEM  (3*X_STAGE)        // 110592

#define QRT    132
#define Q_STAGE (QRT*RS)           // 19008
#define R_ARR_A (16*RS)            // 2304
#define R_STAGE (R_ARR_A + 128*RS) // 20736

__global__ __launch_bounds__(256, 2) void mega_mma() {
    extern __shared__ char smem[];
    __shared__ float rr_[144];
    uint32_t sb = smem_u32(smem);
    int tid = threadIdx.x, lane = tid & 31, wid = tid >> 5;
    int gid = lane >> 2, tig = lane & 3;
    int lrow = lane & 15, lcol = (lane >> 4) << 4;
    int bx = blockIdx.x;

    if (bx < 1280) {
        // ============ GEMM-shaped: cross (bx<1200) or kss-diag =============
        bool diag = bx >= 1200;
        int wm = wid >> 1, wn = wid & 1;
        int nt_t = 0, mt_t = 0, b = 0, local = 0;
        int arowg, browg, bValid;
        const char *A, *B;
        if (!diag) {
            nt_t = bx % 15;
            mt_t = (bx / 15) % 5;
            b    = bx / 75;
            bValid = 1875 - nt_t * 128; if (bValid > 128) bValid = 128;
            arowg = b * 650 + mt_t * 128;
            browg = b * 1875 + nt_t * 128;
            A = (const char*)(g_S + (size_t)arowg * CF);
            B = (const char*)(g_T + (size_t)browg * CF);
        } else {
            local = bx - 1200;             // b*NWAY + w
            arowg = local * NSS;           // rows 0..127 of this class
            browg = arowg;
            bValid = 128;
            A = (const char*)(g_S + (size_t)arowg * CF);
            B = A;
        }

        float acc[2][8][4];
#pragma unroll
        for (int i = 0; i < 2; i++)
#pragma unroll
            for (int j = 0; j < 8; j++)
#pragma unroll
                for (int k = 0; k < 4; k++) acc[i][j][k] = 0.f;

        uint32_t aoff = (wm * 32 + lrow) * RS + lcol;
        uint32_t boff = X_ARR + (wn * 64 + lrow) * RS + lcol;

        auto fill = [&](int stage, int c) {
#pragma unroll
            for (int it = 0; it < 8; it++) {
                int idx = tid + it * 256;      // 2048 tasks exactly
                int arr = idx >> 10;
                int rs  = idx & 1023;
                int row = rs >> 3, seg = rs & 7;
                const char* base = arr ? B : A;
                int valid = arr ? (row < bValid ? 16 : 0) : 16;
                cp16(sb + stage * X_STAGE + arr * X_ARR + row * RS + seg * 16,
                     base + (size_t)row * ROWB + c * 128 + seg * 16, valid);
            }
            CP_COMMIT();
        };

        uint32_t af[2][2][4], bf[2][4][4];
        auto ldfrag = [&](uint32_t base, int buf, int ks) {
#pragma unroll
            for (int mt = 0; mt < 2; mt++)
                ldsm_x4(af[buf][mt], base + aoff + mt * (16 * RS) + ks * 32);
#pragma unroll
            for (int p = 0; p < 4; p++)
                ldsm_x4(bf[buf][p], base + boff + p * (16 * RS) + ks * 32);
        };

        fill(0, 0);
        fill(1, 1);
        int stage = 0;
        for (int c = 0; c < NCH; c++) {
            if (c == NCH - 1) { CP_WAIT0(); } else { CP_WAIT1(); }
            __syncthreads();
            if (c + 2 < NCH) {
                int s2 = stage + 2; if (s2 >= 3) s2 -= 3;
                fill(s2, c + 2);
            }
            uint32_t base = sb + stage * X_STAGE;
            ldfrag(base, 0, 0);
#pragma unroll
            for (int ks = 0; ks < 4; ks++) {
                int cur = ks & 1;
                if (ks < 3) ldfrag(base, cur ^ 1, ks + 1);
#pragma unroll
                for (int p = 0; p < 4; p++)
#pragma unroll
                    for (int mt = 0; mt < 2; mt++) {
                        mma4(acc[mt][p*2+0], af[cur][mt], bf[cur][p][0], bf[cur][p][2]);
                        mma4(acc[mt][p*2+1], af[cur][mt], bf[cur][p][1], bf[cur][p][3]);
                    }
            }
            stage = (stage == 2) ? 0 : stage + 1;
        }

        // epilogue: reuse pipeline smem (cA | cB | per-warp tab slabs)
        float* epi = (float*)smem;   // [0:128)=cA [128:256)=cB [256:384)=tabs
        __syncthreads();
        if (tid < 128) {
            epi[tid] = g_cS[arowg + tid];
            epi[128 + tid] = diag ? g_cS[arowg + tid]
                                  : ((tid < bValid) ? g_cT[browg + tid] : 0.f);
            epi[256 + tid] = 0.f;
        }
        __syncthreads();

        if (!diag) {
            int qb = nt_t * 128;
            int q_base = qb / 25;
            int w_base = (mt_t * 128) / 130;
#pragma unroll
            for (int mt = 0; mt < 2; mt++)
#pragma unroll
            for (int rh = 0; rh < 2; rh++) {
                int row = wm * 32 + mt * 16 + rh * 8 + gid;
                int gs = mt_t * 128 + row;
                int wrel = gs / 130 - w_base;
                float cc = epi[row];
                float run = 0.f;
                int qprev = (qb + wn * 64 + tig * 2) / 25;
#pragma unroll
                for (int nt = 0; nt < 8; nt++)
#pragma unroll
                for (int e = 0; e < 2; e++) {
                    int col = wn * 64 + nt * 8 + tig * 2 + e;
                    int gt = qb + col;
                    int q = gt / 25;
                    if (q != qprev) {
                        atomicAdd(&epi[256 + wid * 16 + wrel * 8 + (qprev - q_base)], run);
                        run = 0.f; qprev = q;
                    }
                    if (gt < 1875)
                        run += multigauss_dot(acc[mt][nt][rh * 2 + e] * cc * epi[128 + col]);
                }
                atomicAdd(&epi[256 + wid * 16 + wrel * 8 + (qprev - q_base)], run);
            }
            __syncthreads();
            if (tid < 16) {
                float v = 0.f;
#pragma unroll
                for (int w8 = 0; w8 < 8; w8++) v += epi[256 + w8 * 16 + tid];
                if (v != 0.f) {
                    int q = q_base + (tid & 7);
                    int w = w_base + (tid >> 3);
                    if (q < NQQ && w < NWAY)
                        atomicAdd(&g_qs_sum[(b * NQQ + q) * NWAY + w], v);
                }
            }
        } else {
            float sum = 0.f;
#pragma unroll
            for (int mt = 0; mt < 2; mt++)
#pragma unroll
            for (int rh = 0; rh < 2; rh++) {
                int row = wm * 32 + mt * 16 + rh * 8 + gid;
                float cc = epi[row];
#pragma unroll
                for (int nt = 0; nt < 8; nt++)
#pragma unroll
                for (int e = 0; e < 2; e++) {
                    int col = wn * 64 + nt * 8 + tig * 2 + e;
                    if (row != col)
                        sum += multigauss_dot(acc[mt][nt][rh * 2 + e] * cc * epi[128 + col]);
                }
            }
#pragma unroll
            for (int o = 16; o > 0; o >>= 1)
                sum += __shfl_down_sync(0xffffffffu, sum, o);
            if (lane == 0) atomicAdd(&g_ss_sum[local], sum);
        }
    } else if (bx < 1520) {
        // ================= kqq: CTA per (b, 5-q group); 5 warps =============
        if (tid >= 160) return;
        int p = bx - 1280;
        int b = p / 15, qg = p % 15;
        int rowg = b * 1875 + qg * 125;
        const char* H = (const char*)(g_T + (size_t)rowg * CF);

        if (tid < 125) rr_[tid] = g_cT[rowg + tid];
        for (int idx = tid; idx < 2 * 7 * 9; idx += 160) {
            int st = idx / 63, rr = (idx % 63) / 9, sg = idx % 9;
            *(uint4*)(smem + st * Q_STAGE + (125 + rr) * RS + sg * 16)
                = make_uint4(0,0,0,0);
        }
        __syncthreads();

        float acc[2][4][4];
#pragma unroll
        for (int i = 0; i < 2; i++)
#pragma unroll
            for (int j = 0; j < 4; j++)
#pragma unroll
                for (int k = 0; k < 4; k++) acc[i][j][k] = 0.f;

        uint32_t woff = (wid * 25 + lrow) * RS + lcol;

        auto fill = [&](int stage, int c) {
#pragma unroll
            for (int it = 0; it < 7; it++) {
                int idx = tid + it * 160;
                if (idx < 1000) {
                    int row = idx >> 3, seg = idx & 7;
                    cp16(sb + stage * Q_STAGE + row * RS + seg * 16,
                         H + (size_t)row * ROWB + c * 128 + seg * 16, 16);
                }
            }
            CP_COMMIT();
        };

        uint32_t af[2][2][4];
        auto ldfrag = [&](uint32_t base, int buf, int ks) {
#pragma unroll
            for (int mt = 0; mt < 2; mt++)
                ldsm_x4(af[buf][mt], base + woff + mt * (16 * RS) + ks * 32);
        };

        fill(0, 0); fill(1, 1);
        for (int c = 0; c < NCH; c++) {
            if (c == NCH - 1) { CP_WAIT0(); } else { CP_WAIT1(); }
            __syncthreads();
            uint32_t base = sb + (c & 1) * Q_STAGE;
            ldfrag(base, 0, 0);
#pragma unroll
            for (int ks = 0; ks < 4; ks++) {
                int cur = ks & 1;
                if (ks < 3) ldfrag(base, cur ^ 1, ks + 1);
#pragma unroll
                for (int pp = 0; pp < 2; pp++)
#pragma unroll
                    for (int mt = 0; mt < 2; mt++) {
                        mma4(acc[mt][pp*2+0], af[cur][mt], af[cur][pp][0], af[cur][pp][2]);
                        mma4(acc[mt][pp*2+1], af[cur][mt], af[cur][pp][1], af[cur][pp][3]);
                    }
            }
            __syncthreads();
            if (c + 2 < NCH) fill((c & 1), c + 2);
        }

        float sum = 0.f;
        int qr = wid * 25;
#pragma unroll
        for (int mt = 0; mt < 2; mt++)
#pragma unroll
        for (int nt = 0; nt < 4; nt++)
#pragma unroll
        for (int rh = 0; rh < 2; rh++)
#pragma unroll
        for (int e = 0; e < 2; e++) {
            int row = mt * 16 + rh * 8 + gid;
            int col = nt * 8 + tig * 2 + e;
            if (row < NQ && col < NQ && row != col)
                sum += multigauss_dot(acc[mt][nt][rh * 2 + e]
                                      * rr_[qr + row] * rr_[qr + col]);
        }
#pragma unroll
        for (int o = 16; o > 0; o >>= 1) sum += __shfl_down_sync(0xffffffffu, sum, o);
        if (lane == 0)
            g_mmd_q[b * NQQ + qg * 5 + wid] = sum * (1.0f / (NQ * (NQ - 1)));
    } else if (bx < 1760) {
        // ================= rem: S rows 640..649 x T tile; 4 warps ==========
        if (tid >= 128) return;
        int local = bx - 1520;
        int nt_t = local % 15, b = local / 15;
        int wn = wid;

        __shared__ float rtab[8];
        __shared__ float rrA[16], rrB[128];

        int bValid = 1875 - nt_t * 128; if (bValid > 128) bValid = 128;
        int arowg = b * 650 + 640;
        int browg = b * 1875 + nt_t * 128;
        const char* A = (const char*)(g_S + (size_t)arowg * CF);
        const char* B = (const char*)(g_T + (size_t)browg * CF);

        if (tid < 8) rtab[tid] = 0.f;
        if (tid < 16) rrA[tid] = (tid < 10) ? g_cS[arowg + tid] : 0.f;
        rrB[tid] = (tid < bValid) ? g_cT[browg + tid] : 0.f;

        float acc[4][4];
#pragma unroll
        for (int j = 0; j < 4; j++)
#pragma unroll
            for (int k = 0; k < 4; k++) acc[j][k] = 0.f;

        uint32_t aoff = lrow * RS + lcol;
        uint32_t boff = R_ARR_A + (wn * 32 + lrow) * RS + lcol;

        auto fill = [&](int stage, int c) {
#pragma unroll
            for (int it = 0; it < 9; it++) {
                int idx = tid + it * 128;
                if (idx < 128) {
                    int row = idx >> 3, seg = idx & 7;
                    cp16(sb + stage * R_STAGE + row * RS + seg * 16,
                         A + (size_t)row * ROWB + c * 128 + seg * 16,
                         row < 10 ? 16 : 0);
                } else if (idx < 1152) {
                    int j = idx - 128;
                    int row = j >> 3, seg = j & 7;
                    cp16(sb + stage * R_STAGE + R_ARR_A + row * RS + seg * 16,
                         B + (size_t)row * ROWB + c * 128 + seg * 16,
                         row < bValid ? 16 : 0);
                }
            }
            CP_COMMIT();
        };

        fill(0, 0);
        fill(1, 1);
        for (int c = 0; c < NCH; c++) {
            if (c == NCH - 1) { CP_WAIT0(); } else { CP_WAIT1(); }
            __syncthreads();
            uint32_t base = sb + (c & 1) * R_STAGE;
#pragma unroll
            for (int ks = 0; ks < 4; ks++) {
                uint32_t af[4], bf[2][4];
                ldsm_x4(af, base + aoff + ks * 32);
#pragma unroll
                for (int p = 0; p < 2; p++)
                    ldsm_x4(bf[p], base + boff + p * (16 * RS) + ks * 32);
#pragma unroll
                for (int p = 0; p < 2; p++) {
                    mma4(acc[p*2+0], af, bf[p][0], bf[p][2]);
                    mma4(acc[p*2+1], af, bf[p][1], bf[p][3]);
                }
            }
            __syncthreads();
            if (c + 2 < NCH) fill((c & 1), c + 2);
        }

        int qb = nt_t * 128;
        int q_base = qb / 25;
#pragma unroll
        for (int rh = 0; rh < 2; rh++) {
            int row = rh * 8 + gid;
            if (row < 10) {
                float cc = rrA[row];
                float run = 0.f;
                int qprev = (qb + wn * 32 + tig * 2) / 25;
#pragma unroll
                for (int j = 0; j < 4; j++)
#pragma unroll
                for (int e = 0; e < 2; e++) {
                    int col = wn * 32 + j * 8 + tig * 2 + e;
                    int gt = qb + col;
                    int q = gt / 25;
                    if (q != qprev) {
                        atomicAdd(&rtab[qprev - q_base], run);
                        run = 0.f; qprev = q;
                    }
                    if (gt < 1875)
                        run += multigauss_dot(acc[j][rh * 2 + e] * cc * rrB[col]);
                }
                atomicAdd(&rtab[qprev - q_base], run);
            }
        }
        __syncthreads();
        if (tid < 8) {
            float v = rtab[tid];
            int q = q_base + tid;
            if (v != 0.f && q < NQQ)
                atomicAdd(&g_qs_sum[(b * NQQ + q) * NWAY + 4], v);
        }
    } else {
        // ============ kss boundary strips: pairs touching rows 128/129 =====
        int local = bx - 1760;               // b*NWAY + w
        int base = local * NSS;
        const __half* S = g_S + (size_t)base * CF;
        float sum = 0.f;
        for (int p = tid; p < 516; p += 256) {
            int i, j;
            if (p < 260) { i = 128 + (p / 130); j = p % 130; }
            else         { int q = p - 260; i = q >> 1; j = 128 + (q & 1); }
            if (i == j) continue;
            const __half2* ra = (const __half2*)(S + (size_t)i * CF);
            const __half2* rb = (const __half2*)(S + (size_t)j * CF);
            float d = 0.f;
#pragma unroll 4
            for (int k = 0; k < CF / 2; k++) {
                float2 fa = __half22float2(ra[k]);
                float2 fb = __half22float2(rb[k]);
                d = fmaf(fa.x, fb.x, d);
                d = fmaf(fa.y, fb.y, d);
            }
            sum += multigauss_dot(d * g_cS[base + i] * g_cS[base + j]);
        }
#pragma unroll
        for (int o = 16; o > 0; o >>= 1)
            sum += __shfl_down_sync(0xffffffffu, sum, o);
        if (lane == 0 && sum != 0.f) atomicAdd(&g_ss_sum[local], sum);
    }
}

// ---------------------------------------------------------------------------
__global__ void combine_kernel(float* __restrict__ out) {
    int idx = blockIdx.x * blockDim.x + threadIdx.x;
    if (idx >= NB * NQQ * NWAY) return;
    int w = idx % NWAY;
    int bq = idx / NWAY;
    int b = bq / NQQ;
    out[idx] = g_ss_sum[b * NWAY + w] * (1.0f / (NSS * (NSS - 1)))
             + g_mmd_q[bq]
             - 2.0f * g_qs_sum[idx] * (1.0f / (NSS * NQ));
}

// ---------------------------------------------------------------------------
extern "C" void kernel_launch(void* const* d_in, const int* in_sizes, int n_in,
                              void* d_out, int out_size) {
    const float* sup = (const float*)d_in[0];
    const float* qry = (const float*)d_in[1];
    float* out = (float*)d_out;
    (void)in_sizes; (void)n_in; (void)out_size;

    cudaFuncSetAttribute(mega_mma, cudaFuncAttributeMaxDynamicSharedMemorySize,
                         X_SMEM);

    norm_kernel<<<(SRN + TRN + 7) / 8, 256>>>(sup, qry);
    mega_mma<<<1840, 256, X_SMEM>>>();
    combine_kernel<<<(NB * NQQ * NWAY + 127) / 128, 128>>>(out);
}

// round 15
// speedup vs baseline: 1.5358x; 1.5358x over previous
#include <cuda_runtime.h>
#include <cuda_fp16.h>
#include <cstdint>

#define NB   16
#define NWAY 5
#define NQ   25
#define NSS  130
#define NQQ  75
#define CF   640
#define SRN  (NB*NWAY*NSS)   // 10400
#define TRN  (NB*NQQ*NQ)     // 30000
#define ROWB (CF*2)          // 1280 B per fp16 row
#define RS   144             // smem row stride (128B data + 16 pad)
#define NCH  10              // chunks of 64 fp16

__device__ __half g_S[SRN*CF];
__device__ __half g_T[TRN*CF];
__device__ float g_rS[SRN];
__device__ float g_rT[TRN];
__device__ float g_ss_sum[NB*NWAY];
__device__ float g_mmd_q[NB*NQQ];
__device__ float g_qs_sum[NB*NQQ*NWAY];

// ---------------------------------------------------------------------------
__device__ __forceinline__ uint32_t smem_u32(const void* p) {
    uint32_t a;
    asm("{ .reg .u64 t; cvta.to.shared.u64 t, %1; cvt.u32.u64 %0, t; }"
        : "=r"(a) : "l"(p));
    return a;
}
__device__ __forceinline__ void ldsm_x4(uint32_t* r, uint32_t addr) {
    asm volatile("ldmatrix.sync.aligned.m8n8.x4.shared.b16 {%0,%1,%2,%3}, [%4];"
                 : "=r"(r[0]), "=r"(r[1]), "=r"(r[2]), "=r"(r[3]) : "r"(addr));
}
__device__ __forceinline__ void mma4(float* c, const uint32_t* a,
                                     uint32_t b0, uint32_t b1) {
    asm volatile(
        "mma.sync.aligned.m16n8k16.row.col.f32.f16.f16.f32 "
        "{%0,%1,%2,%3}, {%4,%5,%6,%7}, {%8,%9}, {%0,%1,%2,%3};"
        : "+f"(c[0]), "+f"(c[1]), "+f"(c[2]), "+f"(c[3])
        : "r"(a[0]), "r"(a[1]), "r"(a[2]), "r"(a[3]), "r"(b0), "r"(b1));
}
__device__ __forceinline__ void cp16(uint32_t dst, const void* src, int szp) {
    asm volatile("cp.async.cg.shared.global [%0], [%1], 16, %2;"
                 :: "r"(dst), "l"(src), "r"(szp));
}
#define CP_COMMIT() asm volatile("cp.async.commit_group;" ::: "memory")
#define CP_WAIT1()  asm volatile("cp.async.wait_group 1;" ::: "memory")
#define CP_WAIT0()  asm volatile("cp.async.wait_group 0;" ::: "memory")

__device__ __forceinline__ float multigauss_dot(float dot) {
    float d2 = fmaxf(2.0f - 2.0f * dot, 0.0f);
    float u  = __expf(-0.125f * d2);
    float u2 = u*u, u4 = u2*u2, u8 = u4*u4, u16 = u8*u8;
    return u + u2 + u4 + u8 + u16;
}

// ---------------------------------------------------------------------------
// normalize (+ zero g_qs_sum): one warp per row -> fp16 row + exact inv-norm
__global__ __launch_bounds__(256) void norm_kernel(
    const float* __restrict__ sup, const float* __restrict__ qry) {
    int gt0 = blockIdx.x * 256 + threadIdx.x;
    if (gt0 < NB * NQQ * NWAY) g_qs_sum[gt0] = 0.f;

    int row = blockIdx.x * 8 + (threadIdx.x >> 5);
    if (row >= SRN + TRN) return;
    int lane = threadIdx.x & 31;

    const float* src;
    __half* dst;
    float* rdst;
    if (row < SRN) {
        src = sup + (size_t)row * CF;
        dst = g_S + (size_t)row * CF;
        rdst = g_rS + row;
    } else {
        int r = row - SRN;
        src = qry + (size_t)r * CF;
        dst = g_T + (size_t)r * CF;
        rdst = g_rT + r;
    }

    float4 v[5];
    float s1 = 0.f, s2 = 0.f;
#pragma unroll
    for (int s = 0; s < 5; s++) {
        v[s] = ((const float4*)src)[s * 32 + lane];
        s1 += v[s].x + v[s].y + v[s].z + v[s].w;
        s2 += v[s].x*v[s].x + v[s].y*v[s].y + v[s].z*v[s].z + v[s].w*v[s].w;
    }
#pragma unroll
    for (int o = 16; o > 0; o >>= 1) {
        s1 += __shfl_xor_sync(0xffffffffu, s1, o);
        s2 += __shfl_xor_sync(0xffffffffu, s2, o);
    }
    float mean = s1 * (1.0f / CF);
    float inv = rsqrtf(s2 - s1 * mean + 1e-12f);

    float hh = 0.f;
    union { __half h[4]; uint2 u; } ph[5];
#pragma unroll
    for (int s = 0; s < 5; s++) {
        float x[4] = {(v[s].x - mean) * inv, (v[s].y - mean) * inv,
                      (v[s].z - mean) * inv, (v[s].w - mean) * inv};
#pragma unroll
        for (int k = 0; k < 4; k++) {
            __half hf = __float2half_rn(x[k]);
            ph[s].h[k] = hf;
            float hv = __half2float(hf);
            hh += hv * hv;
        }
    }
#pragma unroll
    for (int o = 16; o > 0; o >>= 1)
        hh += __shfl_xor_sync(0xffffffffu, hh, o);
    float rcorr = rsqrtf(hh + 1e-12f);

#pragma unroll
    for (int s = 0; s < 5; s++)
        ((uint2*)dst)[s * 32 + lane] = ph[s].u;
    if (lane == 0) *rdst = rcorr;
}

// ---------------------------------------------------------------------------
// mega kernel: blocks [0,1200) cross | [1200,1280) kss | [1280,1520) kqq |
//              [1520,1760) rem.  288 threads, 110592 B dynamic smem.
#define X_ARR   (128*RS)           // 18432
#define X_STAGE (2*X_ARR)          // 36864
#define X_SMEM  (3*X_STAGE)        // 110592

#define SRT    144
#define S_STAGE (SRT*RS)           // 20736
#define QRT    132
#define Q_STAGE (QRT*RS)           // 19008
#define R_ARR_A (16*RS)            // 2304
#define R_STAGE (R_ARR_A + 128*RS) // 20736

__global__ __launch_bounds__(288, 2) void mega_mma() {
    extern __shared__ char smem[];
    __shared__ float red[9];
    __shared__ float rr_[144];
    __shared__ float cAB[256];       // cross: cA[0:128) | cB[128:256)
    uint32_t sb = smem_u32(smem);
    int tid = threadIdx.x, lane = tid & 31, wid = tid >> 5;
    int gid = lane >> 2, tig = lane & 3;
    int lrow = lane & 15, lcol = (lane >> 4) << 4;
    int bx = blockIdx.x;

    if (bx < 1200) {
        // ================= cross: CTA 128x128, 8 warps 4x2 (warp 32x64) ====
        int nt_t = bx % 15;
        int mt_t = (bx / 15) % 5;
        int b    = bx / 75;
        int wm = wid >> 1, wn = wid & 1;

        int bValid = 1875 - nt_t * 128; if (bValid > 128) bValid = 128;
        int arowg = b * 650 + mt_t * 128;
        int browg = b * 1875 + nt_t * 128;
        const char* A = (const char*)(g_S + (size_t)arowg * CF);
        const char* B = (const char*)(g_T + (size_t)browg * CF);

        // warp 8 (idle in the MMA mainloop) prefetches epilogue scales
        if (wid == 8) {
#pragma unroll
            for (int i = 0; i < 4; i++) {
                int t = lane + i * 32;
                cAB[t] = g_rS[arowg + t];
                cAB[128 + t] = (t < bValid) ? g_rT[browg + t] : 0.f;
            }
        }

        float acc[2][8][4];
#pragma unroll
        for (int i = 0; i < 2; i++)
#pragma unroll
            for (int j = 0; j < 8; j++)
#pragma unroll
                for (int k = 0; k < 4; k++) acc[i][j][k] = 0.f;

        uint32_t aoff = (wm * 32 + lrow) * RS + lcol;
        uint32_t boff = X_ARR + (wn * 64 + lrow) * RS + lcol;

        auto fill = [&](int stage, int c) {
#pragma unroll
            for (int it = 0; it < 8; it++) {
                int idx = tid + it * 288;
                if (idx < 2048) {
                    int arr = idx >> 10;
                    int rs  = idx & 1023;
                    int row = rs >> 3, seg = rs & 7;
                    const char* base = arr ? B : A;
                    int valid = arr ? (row < bValid ? 16 : 0) : 16;
                    cp16(sb + stage * X_STAGE + arr * X_ARR + row * RS + seg * 16,
                         base + (size_t)row * ROWB + c * 128 + seg * 16, valid);
                }
            }
            CP_COMMIT();
        };

        uint32_t af[2][2][4], bf[2][4][4];
        auto ldfrag = [&](uint32_t base, int buf, int ks) {
#pragma unroll
            for (int mt = 0; mt < 2; mt++)
                ldsm_x4(af[buf][mt], base + aoff + mt * (16 * RS) + ks * 32);
#pragma unroll
            for (int p = 0; p < 4; p++)
                ldsm_x4(bf[buf][p], base + boff + p * (16 * RS) + ks * 32);
        };

        fill(0, 0);
        fill(1, 1);
        int stage = 0;
        for (int c = 0; c < NCH; c++) {
            if (c == NCH - 1) { CP_WAIT0(); } else { CP_WAIT1(); }
            __syncthreads();
            if (c + 2 < NCH) {
                int s2 = stage + 2; if (s2 >= 3) s2 -= 3;
                fill(s2, c + 2);
            }
            if (wid < 8) {
                uint32_t base = sb + stage * X_STAGE;
                ldfrag(base, 0, 0);
#pragma unroll
                for (int ks = 0; ks < 4; ks++) {
                    int cur = ks & 1;
                    if (ks < 3) ldfrag(base, cur ^ 1, ks + 1);
#pragma unroll
                    for (int p = 0; p < 4; p++)
#pragma unroll
                        for (int mt = 0; mt < 2; mt++) {
                            mma4(acc[mt][p*2+0], af[cur][mt], bf[cur][p][0], bf[cur][p][2]);
                            mma4(acc[mt][p*2+1], af[cur][mt], bf[cur][p][1], bf[cur][p][3]);
                        }
                }
            }
            stage = (stage == 2) ? 0 : stage + 1;
        }

        // epilogue: per-warp tab slabs in (now dead) pipeline smem
        float* epi = (float*)smem;   // [0:128) = tabw[8][16]
        __syncthreads();
        if (tid < 128) epi[tid] = 0.f;
        __syncthreads();

        int qb = nt_t * 128;
        int q_base = qb / 25;
        int w_base = (mt_t * 128) / 130;
        if (wid < 8) {
#pragma unroll
            for (int mt = 0; mt < 2; mt++)
#pragma unroll
            for (int rh = 0; rh < 2; rh++) {
                int row = wm * 32 + mt * 16 + rh * 8 + gid;
                int gs = mt_t * 128 + row;
                int wrel = gs / 130 - w_base;
                float cc = cAB[row];
                float run = 0.f;
                int qprev = (qb + wn * 64 + tig * 2) / 25;
#pragma unroll
                for (int nt = 0; nt < 8; nt++)
#pragma unroll
                for (int e = 0; e < 2; e++) {
                    int col = wn * 64 + nt * 8 + tig * 2 + e;
                    int gt = qb + col;
                    int q = gt / 25;
                    if (q != qprev) {
                        atomicAdd(&epi[wid * 16 + wrel * 8 + (qprev - q_base)], run);
                        run = 0.f; qprev = q;
                    }
                    if (gt < 1875)
                        run += multigauss_dot(acc[mt][nt][rh * 2 + e] * cc * cAB[128 + col]);
                }
                atomicAdd(&epi[wid * 16 + wrel * 8 + (qprev - q_base)], run);
            }
        }
        __syncthreads();
        if (tid < 16) {
            float v = 0.f;
#pragma unroll
            for (int w8 = 0; w8 < 8; w8++) v += epi[w8 * 16 + tid];
            if (v != 0.f) {
                int q = q_base + (tid & 7);
                int w = w_base + (tid >> 3);
                if (q < NQQ && w < NWAY)
                    atomicAdd(&g_qs_sum[(b * NQQ + q) * NWAY + w], v);
            }
        }
    } else if (bx < 1280) {
        // ================= kss: CTA per (b,w); 9 warps 3x3, warp 48x48 =====
        int local = bx - 1200;
        int b = local / NWAY, w = local % NWAY;
        int wm = wid / 3, wn = wid % 3;
        int rowg = (b * NWAY + w) * NSS;
        const char* H = (const char*)(g_S + (size_t)rowg * CF);

        if (tid < 144) rr_[tid] = (tid < NSS) ? g_rS[rowg + tid] : 0.f;
        for (int idx = tid; idx < 2 * 14 * 9; idx += 288) {
            int st = idx / 126, rr = (idx % 126) / 9, sg = idx % 9;
            *(uint4*)(smem + st * S_STAGE + (130 + rr) * RS + sg * 16)
                = make_uint4(0,0,0,0);
        }
        __syncthreads();

        float acc[3][6][4];
#pragma unroll
        for (int i = 0; i < 3; i++)
#pragma unroll
            for (int j = 0; j < 6; j++)
#pragma unroll
                for (int k = 0; k < 4; k++) acc[i][j][k] = 0.f;

        uint32_t aoff = (wm * 48 + lrow) * RS + lcol;
        uint32_t boff = (wn * 48 + lrow) * RS + lcol;

        auto fill = [&](int stage, int c) {
#pragma unroll
            for (int it = 0; it < 4; it++) {
                int idx = tid + it * 288;
                if (idx < 1040) {
                    int row = idx >> 3, seg = idx & 7;
                    cp16(sb + stage * S_STAGE + row * RS + seg * 16,
                         H + (size_t)row * ROWB + c * 128 + seg * 16, 16);
                }
            }
            CP_COMMIT();
        };

        uint32_t af[2][3][4], bf[2][3][4];
        auto ldfrag = [&](uint32_t base, int buf, int ks) {
#pragma unroll
            for (int mt = 0; mt < 3; mt++)
                ldsm_x4(af[buf][mt], base + aoff + mt * (16 * RS) + ks * 32);
#pragma unroll
            for (int p = 0; p < 3; p++)
                ldsm_x4(bf[buf][p], base + boff + p * (16 * RS) + ks * 32);
        };

        fill(0, 0); fill(1, 1);
        for (int c = 0; c < NCH; c++) {
            if (c == NCH - 1) { CP_WAIT0(); } else { CP_WAIT1(); }
            __syncthreads();
            uint32_t base = sb + (c & 1) * S_STAGE;
            ldfrag(base, 0, 0);
#pragma unroll
            for (int ks = 0; ks < 4; ks++) {
                int cur = ks & 1;
                if (ks < 3) ldfrag(base, cur ^ 1, ks + 1);
#pragma unroll
                for (int p = 0; p < 3; p++)
#pragma unroll
                    for (int mt = 0; mt < 3; mt++) {
                        mma4(acc[mt][p*2+0], af[cur][mt], bf[cur][p][0], bf[cur][p][2]);
                        mma4(acc[mt][p*2+1], af[cur][mt], bf[cur][p][1], bf[cur][p][3]);
                    }
            }
            __syncthreads();
            if (c + 2 < NCH) fill((c & 1), c + 2);
        }

        float sum = 0.f;
#pragma unroll
        for (int mt = 0; mt < 3; mt++)
#pragma unroll
        for (int nt = 0; nt < 6; nt++)
#pragma unroll
        for (int rh = 0; rh < 2; rh++)
#pragma unroll
        for (int e = 0; e < 2; e++) {
            int row = wm * 48 + mt * 16 + rh * 8 + gid;
            int col = wn * 48 + nt * 8 + tig * 2 + e;
            if (row < NSS && col < NSS && row != col)
                sum += multigauss_dot(acc[mt][nt][rh * 2 + e] * rr_[row] * rr_[col]);
        }
#pragma unroll
        for (int o = 16; o > 0; o >>= 1) sum += __shfl_down_sync(0xffffffffu, sum, o);
        if (lane == 0) red[wid] = sum;
        __syncthreads();
        if (tid == 0) {
            float t = 0.f;
            for (int i = 0; i < 9; i++) t += red[i];
            g_ss_sum[b * NWAY + w] = t;
        }
    } else if (bx < 1520) {
        // ================= kqq: CTA per (b, 5-q group); 5 warps =============
        if (tid >= 160) return;
        int p = bx - 1280;
        int b = p / 15, qg = p % 15;
        int rowg = b * 1875 + qg * 125;
        const char* H = (const char*)(g_T + (size_t)rowg * CF);

        if (tid < 125) rr_[tid] = g_rT[rowg + tid];
        for (int idx = tid; idx < 2 * 7 * 9; idx += 160) {
            int st = idx / 63, rr = (idx % 63) / 9, sg = idx % 9;
            *(uint4*)(smem + st * Q_STAGE + (125 + rr) * RS + sg * 16)
                = make_uint4(0,0,0,0);
        }
        __syncthreads();

        float acc[2][4][4];
#pragma unroll
        for (int i = 0; i < 2; i++)
#pragma unroll
            for (int j = 0; j < 4; j++)
#pragma unroll
                for (int k = 0; k < 4; k++) acc[i][j][k] = 0.f;

        uint32_t woff = (wid * 25 + lrow) * RS + lcol;

        auto fill = [&](int stage, int c) {
#pragma unroll
            for (int it = 0; it < 7; it++) {
                int idx = tid + it * 160;
                if (idx < 1000) {
                    int row = idx >> 3, seg = idx & 7;
                    cp16(sb + stage * Q_STAGE + row * RS + seg * 16,
                         H + (size_t)row * ROWB + c * 128 + seg * 16, 16);
                }
            }
            CP_COMMIT();
        };

        uint32_t af[2][2][4];
        auto ldfrag = [&](uint32_t base, int buf, int ks) {
#pragma unroll
            for (int mt = 0; mt < 2; mt++)
                ldsm_x4(af[buf][mt], base + woff + mt * (16 * RS) + ks * 32);
        };

        fill(0, 0); fill(1, 1);
        for (int c = 0; c < NCH; c++) {
            if (c == NCH - 1) { CP_WAIT0(); } else { CP_WAIT1(); }
            __syncthreads();
            uint32_t base = sb + (c & 1) * Q_STAGE;
            ldfrag(base, 0, 0);
#pragma unroll
            for (int ks = 0; ks < 4; ks++) {
                int cur = ks & 1;
                if (ks < 3) ldfrag(base, cur ^ 1, ks + 1);
#pragma unroll
                for (int pp = 0; pp < 2; pp++)
#pragma unroll
                    for (int mt = 0; mt < 2; mt++) {
                        mma4(acc[mt][pp*2+0], af[cur][mt], af[cur][pp][0], af[cur][pp][2]);
                        mma4(acc[mt][pp*2+1], af[cur][mt], af[cur][pp][1], af[cur][pp][3]);
                    }
            }
            __syncthreads();
            if (c + 2 < NCH) fill((c & 1), c + 2);
        }

        float sum = 0.f;
        int qr = wid * 25;
#pragma unroll
        for (int mt = 0; mt < 2; mt++)
#pragma unroll
        for (int nt = 0; nt < 4; nt++)
#pragma unroll
        for (int rh = 0; rh < 2; rh++)
#pragma unroll
        for (int e = 0; e < 2; e++) {
            int row = mt * 16 + rh * 8 + gid;
            int col = nt * 8 + tig * 2 + e;
            if (row < NQ && col < NQ && row != col)
                sum += multigauss_dot(acc[mt][nt][rh * 2 + e]
                                      * rr_[qr + row] * rr_[qr + col]);
        }
#pragma unroll
        for (int o = 16; o > 0; o >>= 1) sum += __shfl_down_sync(0xffffffffu, sum, o);
        if (lane == 0)
            g_mmd_q[b * NQQ + qg * 5 + wid] = sum * (1.0f / (NQ * (NQ - 1)));
    } else {
        // ================= rem: S rows 640..649 x T tile; 4 warps ==========
        if (tid >= 128) return;
        int local = bx - 1520;
        int nt_t = local % 15, b = local / 15;
        int wn = wid;

        __shared__ float rtab[8];
        __shared__ float rrA[16], rrB[128];

        int bValid = 1875 - nt_t * 128; if (bValid > 128) bValid = 128;
        int arowg = b * 650 + 640;
        int browg = b * 1875 + nt_t * 128;
        const char* A = (const char*)(g_S + (size_t)arowg * CF);
        const char* B = (const char*)(g_T + (size_t)browg * CF);

        if (tid < 8) rtab[tid] = 0.f;
        if (tid < 16) rrA[tid] = (tid < 10) ? g_rS[arowg + tid] : 0.f;
        rrB[tid] = (tid < bValid) ? g_rT[browg + tid] : 0.f;

        float acc[4][4];
#pragma unroll
        for (int j = 0; j < 4; j++)
#pragma unroll
            for (int k = 0; k < 4; k++) acc[j][k] = 0.f;

        uint32_t aoff = lrow * RS + lcol;
        uint32_t boff = R_ARR_A + (wn * 32 + lrow) * RS + lcol;

        auto fill = [&](int stage, int c) {
#pragma unroll
            for (int it = 0; it < 9; it++) {
                int idx = tid + it * 128;
                if (idx < 128) {
                    int row = idx >> 3, seg = idx & 7;
                    cp16(sb + stage * R_STAGE + row * RS + seg * 16,
                         A + (size_t)row * ROWB + c * 128 + seg * 16,
                         row < 10 ? 16 : 0);
                } else if (idx < 1152) {
                    int j = idx - 128;
                    int row = j >> 3, seg = j & 7;
                    cp16(sb + stage * R_STAGE + R_ARR_A + row * RS + seg * 16,
                         B + (size_t)row * ROWB + c * 128 + seg * 16,
                         row < bValid ? 16 : 0);
                }
            }
            CP_COMMIT();
        };

        fill(0, 0);
        fill(1, 1);
        for (int c = 0; c < NCH; c++) {
            if (c == NCH - 1) { CP_WAIT0(); } else { CP_WAIT1(); }
            __syncthreads();
            uint32_t base = sb + (c & 1) * R_STAGE;
#pragma unroll
            for (int ks = 0; ks < 4; ks++) {
                uint32_t af[4], bf[2][4];
                ldsm_x4(af, base + aoff + ks * 32);
#pragma unroll
                for (int p = 0; p < 2; p++)
                    ldsm_x4(bf[p], base + boff + p * (16 * RS) + ks * 32);
#pragma unroll
                for (int p = 0; p < 2; p++) {
                    mma4(acc[p*2+0], af, bf[p][0], bf[p][2]);
                    mma4(acc[p*2+1], af, bf[p][1], bf[p][3]);
                }
            }
            __syncthreads();
            if (c + 2 < NCH) fill((c & 1), c + 2);
        }

        int qb = nt_t * 128;
        int q_base = qb / 25;
#pragma unroll
        for (int rh = 0; rh < 2; rh++) {
            int row = rh * 8 + gid;
            if (row < 10) {
                float cc = rrA[row];
                float run = 0.f;
                int qprev = (qb + wn * 32 + tig * 2) / 25;
#pragma unroll
                for (int j = 0; j < 4; j++)
#pragma unroll
                for (int e = 0; e < 2; e++) {
                    int col = wn * 32 + j * 8 + tig * 2 + e;
                    int gt = qb + col;
                    int q = gt / 25;
                    if (q != qprev) {
                        atomicAdd(&rtab[qprev - q_base], run);
                        run = 0.f; qprev = q;
                    }
                    if (gt < 1875)
                        run += multigauss_dot(acc[j][rh * 2 + e] * cc * rrB[col]);
                }
                atomicAdd(&rtab[qprev - q_base], run);
            }
        }
        __syncthreads();
        if (tid < 8) {
            float v = rtab[tid];
            int q = q_base + tid;
            if (v != 0.f && q < NQQ)
                atomicAdd(&g_qs_sum[(b * NQQ + q) * NWAY + 4], v);
        }
    }
}

// ---------------------------------------------------------------------------
__global__ void combine_kernel(float* __restrict__ out) {
    int idx = blockIdx.x * blockDim.x + threadIdx.x;
    if (idx >= NB * NQQ * NWAY) return;
    int w = idx % NWAY;
    int bq = idx / NWAY;
    int b = bq / NQQ;
    out[idx] = g_ss_sum[b * NWAY + w] * (1.0f / (NSS * (NSS - 1)))
             + g_mmd_q[bq]
             - 2.0f * g_qs_sum[idx] * (1.0f / (NSS * NQ));
}

// ---------------------------------------------------------------------------
extern "C" void kernel_launch(void* const* d_in, const int* in_sizes, int n_in,
                              void* d_out, int out_size) {
    const float* sup = (const float*)d_in[0];
    const float* qry = (const float*)d_in[1];
    float* out = (float*)d_out;
    (void)in_sizes; (void)n_in; (void)out_size;

    cudaFuncSetAttribute(mega_mma, cudaFuncAttributeMaxDynamicSharedMemorySize,
                         X_SMEM);

    norm_kernel<<<(SRN + TRN + 7) / 8, 256>>>(sup, qry);
    mega_mma<<<1760, 288, X_SMEM>>>();
    combine_kernel<<<(NB * NQQ * NWAY + 127) / 128, 128>>>(out);
}